// round 4
// baseline (speedup 1.0000x reference)
#include <cuda_runtime.h>
#include <cstdint>

// Problem constants (fixed by setup_inputs)
#define BATCH 8
#define HDIM  64
#define WDIM  64
#define CDIM  128
#define FDIM  128
#define KNUM  9
#define NPIX  (BATCH * HDIM * WDIM)      // 32768
#define PIX_PER_CTA 128
#define NCTA  (NPIX / PIX_PER_CTA)       // 256

#define PADK 132                          // padded K stride (floats) for bank-conflict-free frags
#define AS_FLOATS (128 * PADK)            // 16896
#define SMEM_FLOATS (2 * AS_FLOATS + 128) // As + Bs + bias
#define SMEM_BYTES (SMEM_FLOATS * 4)      // 135680

__device__ __forceinline__ uint32_t f2tf32(float f) {
    uint32_t r;
    asm("cvt.rna.tf32.f32 %0, %1;" : "=r"(r) : "f"(f));
    return r;
}

// m16n8k8 tf32 mma: D = A*B + D. A row-major 16x8, B col-major 8x8.
__device__ __forceinline__ void mma_tf32(float d[4], const uint32_t a[4], const uint32_t b[2]) {
    asm volatile(
        "mma.sync.aligned.m16n8k8.row.col.f32.tf32.tf32.f32 "
        "{%0,%1,%2,%3}, {%4,%5,%6,%7}, {%8,%9}, {%0,%1,%2,%3};"
        : "+f"(d[0]), "+f"(d[1]), "+f"(d[2]), "+f"(d[3])
        : "r"(a[0]), "r"(a[1]), "r"(a[2]), "r"(a[3]), "r"(b[0]), "r"(b[1]));
}

// TF build(): stack(meshgrid(ij)).reshape(-1,2) pairs:
// (0,0),(0,1),(1,1),(2,2),(2,0),(1,2),(0,1),(2,0),(1,2)
static __device__ const float KOFF_I[KNUM] = {0.f, 0.f, 1.f, 2.f, 2.f, 1.f, 0.f, 2.f, 1.f};
static __device__ const float KOFF_J[KNUM] = {0.f, 1.f, 1.f, 2.f, 0.f, 2.f, 1.f, 0.f, 2.f};

// Pre-transposed + tf32-rounded weights: g_Wt[kn][f][c], 9 * 128 * 128 u32 = 576 KB.
__device__ uint32_t g_Wt[KNUM * 128 * 128];

__global__ void prep_weights_kernel(const float* __restrict__ Wsrc) {
    int idx = blockIdx.x * 256 + threadIdx.x;
    if (idx >= KNUM * 128 * 128) return;
    int kn = idx >> 14;
    int r  = idx & 16383;
    int f  = r >> 7;    // output-feature row (N)
    int c  = r & 127;   // channel col (K)
    g_Wt[kn * 16384 + f * 128 + c] = f2tf32(Wsrc[(kn * 128 + c) * 128 + f]);
}

__global__ __launch_bounds__(256, 1)
void deform_conv_kernel(const float* __restrict__ xin,
                        const float* __restrict__ off,
                        const float* __restrict__ bias,
                        float* __restrict__ out) {
    extern __shared__ float smf[];
    float* As   = smf;                 // [128][PADK] sampled A tile (tf32 bits)
    float* Bs   = smf + AS_FLOATS;     // [128][PADK] weight tile Wt[f][c] (tf32 bits)
    float* bsm  = smf + 2 * AS_FLOATS; // [128] bias

    const int tid = threadIdx.x;
    const int wid = tid >> 5;
    const int lid = tid & 31;
    const int g   = lid >> 2;   // groupID 0..7
    const int tig = lid & 3;    // thread-in-group 0..3
    const int wm  = wid & 3;    // warp row block (32 pixels each)
    const int wn  = wid >> 2;   // warp col block (64 F each)

    if (tid < 128) bsm[tid] = bias[tid];

    const int pix0 = blockIdx.x * PIX_PER_CTA;

    float acc[2][8][4];
    #pragma unroll
    for (int mt = 0; mt < 2; mt++)
        #pragma unroll
        for (int nt = 0; nt < 8; nt++)
            #pragma unroll
            for (int q = 0; q < 4; q++) acc[mt][nt][q] = 0.0f;

    __syncthreads();

    for (int n = 0; n < KNUM; n++) {
        // ---- Stage B: linear copy of pre-rounded Wt[n] into padded SMEM ----
        {
            const float4* wsrc = (const float4*)(g_Wt + n * 16384);
            #pragma unroll
            for (int i = 0; i < 16; i++) {
                int e = tid + i * 256;          // float4 index, 0..4095
                float4 v = wsrc[e];
                int row = e >> 5;               // f row
                int k4  = (e & 31) * 4;         // c col
                *(float4*)(Bs + row * PADK + k4) = v;
            }
        }

        // ---- Stage A: bilinear sample 128 pixels x 128 channels ----
        // One warp per pixel (16 pixels/warp); each lane handles 4 channels.
        const float ki = KOFF_I[n];
        const float kj = KOFF_J[n];
        #pragma unroll
        for (int i = 0; i < 16; i++) {
            int p = wid * 16 + i;          // local pixel 0..127
            int P = pix0 + p;              // global pixel
            int bb = P >> 12;
            int hh = (P >> 6) & 63;
            int ww = P & 63;
            float offr = __ldg(&off[P * 18 + 2 * n]);
            float offc = __ldg(&off[P * 18 + 2 * n + 1]);
            float y  = fminf(fmaxf((float)(hh - 1) + ki + offr, 0.0f), 63.0f);
            float xf = fminf(fmaxf((float)(ww - 1) + kj + offc, 0.0f), 63.0f);
            float y0f = floorf(y), x0f = floorf(xf);
            int y0 = (int)y0f, y1 = (int)ceilf(y);
            int x0 = (int)x0f, x1 = (int)ceilf(xf);
            float fy = y - y0f, fx = xf - x0f;

            const float4* base = (const float4*)xin + (size_t)bb * 131072;
            float4 lt = base[(y0 * 64 + x0) * 32 + lid];
            float4 rt = base[(y1 * 64 + x0) * 32 + lid];
            float4 lb = base[(y0 * 64 + x1) * 32 + lid];
            float4 rb = base[(y1 * 64 + x1) * 32 + lid];

            float4 vt, vb, v;
            vt.x = fmaf(rt.x - lt.x, fy, lt.x);
            vt.y = fmaf(rt.y - lt.y, fy, lt.y);
            vt.z = fmaf(rt.z - lt.z, fy, lt.z);
            vt.w = fmaf(rt.w - lt.w, fy, lt.w);
            vb.x = fmaf(rb.x - lb.x, fy, lb.x);
            vb.y = fmaf(rb.y - lb.y, fy, lb.y);
            vb.z = fmaf(rb.z - lb.z, fy, lb.z);
            vb.w = fmaf(rb.w - lb.w, fy, lb.w);
            v.x = fmaf(vb.x - vt.x, fx, vt.x);
            v.y = fmaf(vb.y - vt.y, fx, vt.y);
            v.z = fmaf(vb.z - vt.z, fx, vt.z);
            v.w = fmaf(vb.w - vt.w, fx, vt.w);

            uint4 o;
            o.x = f2tf32(v.x);
            o.y = f2tf32(v.y);
            o.z = f2tf32(v.z);
            o.w = f2tf32(v.w);
            *(uint4*)(As + p * PADK + lid * 4) = o;
        }
        __syncthreads();

        // ---- MMA: warp tile 32(M) x 64(N), 16 k-steps of 8 ----
        const float* Aw = As + (wm * 32) * PADK;
        const float* Bw = Bs + (wn * 64) * PADK;
        #pragma unroll 4
        for (int ks = 0; ks < 16; ks++) {
            int k0 = ks * 8;
            uint32_t afr[2][4];
            #pragma unroll
            for (int mt = 0; mt < 2; mt++) {
                const float* ar = Aw + (mt * 16 + g) * PADK + k0 + tig;
                afr[mt][0] = __float_as_uint(ar[0]);
                afr[mt][1] = __float_as_uint(ar[8 * PADK]);
                afr[mt][2] = __float_as_uint(ar[4]);
                afr[mt][3] = __float_as_uint(ar[8 * PADK + 4]);
            }
            uint32_t bfr[8][2];
            #pragma unroll
            for (int nt = 0; nt < 8; nt++) {
                const float* br = Bw + (nt * 8 + g) * PADK + k0 + tig;
                bfr[nt][0] = __float_as_uint(br[0]);
                bfr[nt][1] = __float_as_uint(br[4]);
            }
            #pragma unroll
            for (int mt = 0; mt < 2; mt++)
                #pragma unroll
                for (int nt = 0; nt < 8; nt++)
                    mma_tf32(acc[mt][nt], afr[mt], bfr[nt]);
        }
        __syncthreads();
    }

    // ---- Epilogue: add bias, store fp32 output ----
    #pragma unroll
    for (int mt = 0; mt < 2; mt++) {
        #pragma unroll
        for (int nt = 0; nt < 8; nt++) {
            int col = wn * 64 + nt * 8 + tig * 2;
            float b0 = bsm[col], b1 = bsm[col + 1];
            int row = pix0 + wm * 32 + mt * 16 + g;
            float2 v0 = make_float2(acc[mt][nt][0] + b0, acc[mt][nt][1] + b1);
            float2 v1 = make_float2(acc[mt][nt][2] + b0, acc[mt][nt][3] + b1);
            *(float2*)(out + (size_t)row * FDIM + col) = v0;
            *(float2*)(out + (size_t)(row + 8) * FDIM + col) = v1;
        }
    }
}

extern "C" void kernel_launch(void* const* d_in, const int* in_sizes, int n_in,
                              void* d_out, int out_size) {
    const float* x   = (const float*)d_in[0];
    const float* off = (const float*)d_in[1];
    const float* Wk  = (const float*)d_in[2];
    const float* b   = (const float*)d_in[3];
    float* out = (float*)d_out;

    cudaFuncSetAttribute(deform_conv_kernel,
                         cudaFuncAttributeMaxDynamicSharedMemorySize, SMEM_BYTES);

    prep_weights_kernel<<<(KNUM * 128 * 128 + 255) / 256, 256>>>(Wk);
    deform_conv_kernel<<<NCTA, 256, SMEM_BYTES>>>(x, off, b, out);
}